// round 17
// baseline (speedup 1.0000x reference)
#include <cuda_runtime.h>
#include <cuda_fp16.h>

// AreaSelfAttention fused kernel, round 17:
//   all GEMMs fp16 tensor cores (softmax exact fp32, warp-local);
//   TWO windows per CTA: warps 0-3 -> window 0, warps 4-7 -> window 1,
//   synced only via named barriers (bar.sync g+1,128). Groups drift out of
//   phase -> tensor / L1 / fma pipes overlap across groups.
// out = gamma * (Wv @ (Xw @ attn^T) + bv) + x

#define Cc   256
#define Hh   252
#define Ww   252
#define Aa   8
#define LDH  72      // fp16 row stride (halves) -> 144B rows, conflict-free ldsm

// per-window smem region (55296 B): qkh | ath | Xh (y overlays Xh)
#define WOFF_QKH 0
#define WOFF_ATH 9216
#define WOFF_XH  18432
#define WIN_BYTES 55296
#define SMEM_BYTES (2 * WIN_BYTES)   // 110592 -> 2 CTAs/SM

// Fragment-packed fp16 weights (prep kernel fills once per launch).
// reg r of lane = A[mt*16 + gid + 8*(r&1)][ks*16 + 2*tg + 8*(r>>1)]
__device__ uint4 Wqk_pk4[4 * 16 * 32];     // [Wq;Wk] 64x256
__device__ uint4 Wv_pk4[16 * 16 * 32];     // Wv 256x256

__global__ void prep_pack(const float* __restrict__ Wq,
                          const float* __restrict__ Wk,
                          const float* __restrict__ Wv) {
    int u = blockIdx.x * 256 + threadIdx.x;      // grid 160 -> 40960 b32 outputs
    if (u < 8192) {
        int r = u & 3, lane = (u >> 2) & 31, ks = (u >> 7) & 15, mt = u >> 11;
        int gid = lane >> 2, tg = lane & 3;
        int row = mt * 16 + gid + 8 * (r & 1);
        int col = ks * 16 + 2 * tg + 8 * (r >> 1);
        const float* src = (row < 32) ? (Wq + row * Cc) : (Wk + (row - 32) * Cc);
        __half2 h = __floats2half2_rn(src[col], src[col + 1]);
        ((unsigned*)Wqk_pk4)[u] = *(unsigned*)&h;
    } else {
        int v = u - 8192;
        int r = v & 3, lane = (v >> 2) & 31, ks = (v >> 7) & 15, mt = v >> 11;
        int gid = lane >> 2, tg = lane & 3;
        int row = mt * 16 + gid + 8 * (r & 1);
        int col = ks * 16 + 2 * tg + 8 * (r >> 1);
        const float* src = Wv + (size_t)row * Cc;
        __half2 h = __floats2half2_rn(src[col], src[col + 1]);
        ((unsigned*)Wv_pk4)[v] = *(unsigned*)&h;
    }
}

static __device__ __forceinline__ void mma16816(float* d, const unsigned* a,
                                                unsigned b0, unsigned b1) {
    asm volatile(
        "mma.sync.aligned.m16n8k16.row.col.f32.f16.f16.f32 "
        "{%0,%1,%2,%3}, {%4,%5,%6,%7}, {%8,%9}, {%0,%1,%2,%3};"
        : "+f"(d[0]), "+f"(d[1]), "+f"(d[2]), "+f"(d[3])
        : "r"(a[0]), "r"(a[1]), "r"(a[2]), "r"(a[3]), "r"(b0), "r"(b1));
}
static __device__ __forceinline__ unsigned cvsm(const void* p) {
    return (unsigned)__cvta_generic_to_shared(p);
}
static __device__ __forceinline__ void ldsm_x4(unsigned* r, unsigned a) {
    asm volatile("ldmatrix.sync.aligned.m8n8.x4.shared.b16 {%0,%1,%2,%3}, [%4];"
                 : "=r"(r[0]), "=r"(r[1]), "=r"(r[2]), "=r"(r[3]) : "r"(a));
}
static __device__ __forceinline__ void ldsm_x4t(unsigned* r, unsigned a) {
    asm volatile("ldmatrix.sync.aligned.m8n8.x4.trans.shared.b16 {%0,%1,%2,%3}, [%4];"
                 : "=r"(r[0]), "=r"(r[1]), "=r"(r[2]), "=r"(r[3]) : "r"(a));
}
static __device__ __forceinline__ void group_bar(int g) {
    asm volatile("bar.sync %0, %1;" :: "r"(g + 1), "r"(128) : "memory");
}

__global__ __launch_bounds__(256, 2)
void area_attn_kernel(const float* __restrict__ x,
                      const float* __restrict__ bq, const float* __restrict__ bk,
                      const float* __restrict__ bv,
                      const float* __restrict__ gamma,
                      float* __restrict__ out)
{
    extern __shared__ char smraw[];

    const int t    = threadIdx.x;
    const int w    = t >> 5;
    const int g    = w >> 2;               // group = window slot (0 or 1)
    const int wl   = w & 3;                // warp within group
    const int tl   = t & 127;              // thread within group
    const int lane = t & 31;
    const int gid  = lane >> 2;
    const int tg   = lane & 3;
    const int q4   = lane >> 3;
    const int row8 = lane & 7;
    const int l15  = lane & 15;
    const int lhi8 = (lane >> 4) << 3;     // 0 or 8

    char*   wbase = smraw + g * WIN_BYTES;
    __half* qkh   = (__half*)(wbase + WOFF_QKH); // [64][LDH] q 0..31, k 32..63
    __half* ath   = (__half*)(wbase + WOFF_ATH); // [64][LDH] attn fp16
    __half* Xh    = (__half*)(wbase + WOFF_XH);  // [256][LDH] window fp16
    __half* y     = Xh;                          // phase-3 output overlays Xh

    const int win = blockIdx.x * 2 + g;    // 4096 windows = 4 * 32 * 32
    const int bi  = win >> 10;
    const int hi  = (win >> 5) & 31;
    const int wi  = win & 31;

    const float* xb = x + (size_t)bi * Cc * Hh * Ww;

    // ---------------- Phase 0: load x window -> Xh (fp16, zero-padded) -----
    #pragma unroll
    for (int it = 0; it < 32; ++it) {
        int idx4 = tl + (it << 7);
        int c    = idx4 >> 4;
        int rem  = idx4 & 15;
        int iy   = rem >> 1;
        int ix4  = (rem & 1) << 2;
        int gy   = hi * Aa + iy;
        int gx   = wi * Aa + ix4;
        float4 v = make_float4(0.f, 0.f, 0.f, 0.f);
        if (gy < Hh && gx + 3 < Ww)
            v = *(const float4*)(xb + ((size_t)c * Hh + gy) * Ww + gx);
        __half2 h0 = __floats2half2_rn(v.x, v.y);
        __half2 h1 = __floats2half2_rn(v.z, v.w);
        uint2 pk;
        pk.x = *(unsigned*)&h0; pk.y = *(unsigned*)&h1;
        *(uint2*)(Xh + c * LDH + (rem << 2)) = pk;
    }
    group_bar(g);

    // ---------------- Phase 1: qkh = fp16([Wq;Wk] @ Xw + bias) via MMA -----
    // warp wl: m-tile wl (16 rows), FULL n = 64 positions, K=256.
    {
        float d[8][4];
        #pragma unroll
        for (int nt = 0; nt < 8; ++nt)
            #pragma unroll
            for (int r = 0; r < 4; ++r) d[nt][r] = 0.f;

        uint4 av = Wqk_pk4[(wl * 16) * 32 + lane];
        unsigned bb[2][4][4];
        {
            unsigned b0 = cvsm(Xh + l15 * LDH + lhi8);
            #pragma unroll
            for (int p = 0; p < 4; ++p) ldsm_x4t(bb[0][p], b0 + p * 32);
        }
        #pragma unroll
        for (int ks = 0; ks < 16; ++ks) {
            const int cur = ks & 1, nxt = cur ^ 1;
            uint4 nx;
            if (ks < 15) {
                unsigned bn = cvsm(Xh + ((ks + 1) * 16 + l15) * LDH + lhi8);
                #pragma unroll
                for (int p = 0; p < 4; ++p) ldsm_x4t(bb[nxt][p], bn + p * 32);
                nx = Wqk_pk4[(wl * 16 + ks + 1) * 32 + lane];
            }
            #pragma unroll
            for (int p = 0; p < 4; ++p) {
                mma16816(d[2 * p],     (const unsigned*)&av, bb[cur][p][0], bb[cur][p][1]);
                mma16816(d[2 * p + 1], (const unsigned*)&av, bb[cur][p][2], bb[cur][p][3]);
            }
            if (ks < 15) av = nx;
        }
        const int oc0 = wl * 16 + gid;
        const int oc1 = oc0 + 8;
        float bb0 = (wl < 2) ? bq[oc0] : bk[oc0 - 32];
        float bb1 = (wl < 2) ? bq[oc1] : bk[oc1 - 32];
        #pragma unroll
        for (int nt = 0; nt < 8; ++nt) {
            int pos = nt * 8 + 2 * tg;
            *(__half2*)(qkh + oc0 * LDH + pos) = __floats2half2_rn(d[nt][0] + bb0, d[nt][1] + bb0);
            *(__half2*)(qkh + oc1 * LDH + pos) = __floats2half2_rn(d[nt][2] + bb1, d[nt][3] + bb1);
        }
    }
    group_bar(g);

    // ---------------- Phase 2: logits + warp-local softmax -----------------
    // warp wl: i-tile wl (16 rows), FULL j = 64 -> row reductions in-warp.
    {
        float d[8][4];
        #pragma unroll
        for (int nt = 0; nt < 8; ++nt)
            #pragma unroll
            for (int r = 0; r < 4; ++r) d[nt][r] = 0.f;

        #pragma unroll
        for (int ks = 0; ks < 2; ++ks) {
            unsigned a[4];
            ldsm_x4t(a, cvsm(qkh + (ks * 16 + (q4 >> 1) * 8 + row8) * LDH
                                 + wl * 16 + (q4 & 1) * 8));
            unsigned baddr = cvsm(qkh + (32 + ks * 16 + l15) * LDH + lhi8);
            #pragma unroll
            for (int p = 0; p < 4; ++p) {
                unsigned bbq[4];
                ldsm_x4t(bbq, baddr + p * 32);
                mma16816(d[2 * p],     a, bbq[0], bbq[1]);
                mma16816(d[2 * p + 1], a, bbq[2], bbq[3]);
            }
        }

        const int iA = wl * 16 + gid;
        const int iB = iA + 8;
        float mA = d[0][0], mB = d[0][2];
        #pragma unroll
        for (int nt = 0; nt < 8; ++nt) {
            mA = fmaxf(mA, fmaxf(d[nt][0], d[nt][1]));
            mB = fmaxf(mB, fmaxf(d[nt][2], d[nt][3]));
        }
        mA = fmaxf(mA, __shfl_xor_sync(0xffffffffu, mA, 1));
        mA = fmaxf(mA, __shfl_xor_sync(0xffffffffu, mA, 2));
        mB = fmaxf(mB, __shfl_xor_sync(0xffffffffu, mB, 1));
        mB = fmaxf(mB, __shfl_xor_sync(0xffffffffu, mB, 2));
        float sA = 0.f, sB = 0.f;
        #pragma unroll
        for (int nt = 0; nt < 8; ++nt) {
            d[nt][0] = __expf(d[nt][0] - mA); sA += d[nt][0];
            d[nt][1] = __expf(d[nt][1] - mA); sA += d[nt][1];
            d[nt][2] = __expf(d[nt][2] - mB); sB += d[nt][2];
            d[nt][3] = __expf(d[nt][3] - mB); sB += d[nt][3];
        }
        sA += __shfl_xor_sync(0xffffffffu, sA, 1);
        sA += __shfl_xor_sync(0xffffffffu, sA, 2);
        sB += __shfl_xor_sync(0xffffffffu, sB, 1);
        sB += __shfl_xor_sync(0xffffffffu, sB, 2);
        float facA = 1.0f / sA;
        float facB = 1.0f / sB;
        #pragma unroll
        for (int nt = 0; nt < 8; ++nt) {
            int j = nt * 8 + 2 * tg;
            *(__half2*)(ath + iA * LDH + j) =
                __floats2half2_rn(d[nt][0] * facA, d[nt][1] * facA);
            *(__half2*)(ath + iB * LDH + j) =
                __floats2half2_rn(d[nt][2] * facB, d[nt][3] * facB);
        }
    }
    group_bar(g);

    // ---------------- Phase 3: y = Xw @ attn^T via MMA; y overlays Xh ------
    // warp wl: e-strip [64*wl, +64), halves of 32 e-rows. Half reads its own
    // Xh rows fully before overwriting them with y; rows are warp-private.
    #pragma unroll
    for (int h = 0; h < 2; ++h) {
        float d[2][8][4];
        #pragma unroll
        for (int m = 0; m < 2; ++m)
            #pragma unroll
            for (int nt = 0; nt < 8; ++nt)
                #pragma unroll
                for (int r = 0; r < 4; ++r) d[m][nt][r] = 0.f;

        const int ebase = wl * 64 + h * 32;
        #pragma unroll
        for (int ks = 0; ks < 4; ++ks) {
            const int j0 = ks * 16;
            unsigned a[2][4];
            #pragma unroll
            for (int m = 0; m < 2; ++m)
                ldsm_x4(a[m], cvsm(Xh + (ebase + m * 16 + (q4 & 1) * 8 + row8) * LDH
                                       + j0 + (q4 >> 1) * 8));
            #pragma unroll
            for (int ntp = 0; ntp < 4; ++ntp) {
                unsigned bb[4];
                ldsm_x4(bb, cvsm(ath + (ntp * 16 + lhi8 + row8) * LDH
                                     + j0 + (q4 & 1) * 8));
                #pragma unroll
                for (int m = 0; m < 2; ++m) {
                    mma16816(d[m][2 * ntp],     a[m], bb[0], bb[1]);
                    mma16816(d[m][2 * ntp + 1], a[m], bb[2], bb[3]);
                }
            }
        }
        #pragma unroll
        for (int m = 0; m < 2; ++m) {
            int e = ebase + m * 16 + gid;
            #pragma unroll
            for (int nt = 0; nt < 8; ++nt) {
                int i = nt * 8 + 2 * tg;
                *(__half2*)(y +  e      * LDH + i) = __floats2half2_rn(d[m][nt][0], d[m][nt][1]);
                *(__half2*)(y + (e + 8) * LDH + i) = __floats2half2_rn(d[m][nt][2], d[m][nt][3]);
            }
        }
    }
    group_bar(g);

    // ---------------- Phase 4: out = Wv @ y via MMA + epilogue -------------
    // warp wl: c-strip [64*wl, +64), halves of 32 c-rows; weights prefetched.
    {
        const float gma = gamma[0];
        float* ob = out + (size_t)bi * Cc * Hh * Ww;
        #pragma unroll
        for (int h = 0; h < 2; ++h) {
            float d[2][8][4];
            #pragma unroll
            for (int m = 0; m < 2; ++m)
                #pragma unroll
                for (int nt = 0; nt < 8; ++nt)
                    #pragma unroll
                    for (int r = 0; r < 4; ++r) d[m][nt][r] = 0.f;

            const int mtg = wl * 4 + h * 2;        // global 16-row tile index
            uint4 av0 = Wv_pk4[((mtg + 0) * 16) * 32 + lane];
            uint4 av1 = Wv_pk4[((mtg + 1) * 16) * 32 + lane];
            #pragma unroll
            for (int ks = 0; ks < 16; ++ks) {
                uint4 nx0, nx1;
                if (ks < 15) {
                    nx0 = Wv_pk4[((mtg + 0) * 16 + ks + 1) * 32 + lane];
                    nx1 = Wv_pk4[((mtg + 1) * 16 + ks + 1) * 32 + lane];
                }
                unsigned baddr = cvsm(y + (ks * 16 + l15) * LDH + lhi8);
                #pragma unroll
                for (int ntp = 0; ntp < 4; ++ntp) {
                    unsigned bb[4];
                    ldsm_x4t(bb, baddr + ntp * 32);
                    mma16816(d[0][2 * ntp],     (const unsigned*)&av0, bb[0], bb[1]);
                    mma16816(d[0][2 * ntp + 1], (const unsigned*)&av0, bb[2], bb[3]);
                    mma16816(d[1][2 * ntp],     (const unsigned*)&av1, bb[0], bb[1]);
                    mma16816(d[1][2 * ntp + 1], (const unsigned*)&av1, bb[2], bb[3]);
                }
                if (ks < 15) { av0 = nx0; av1 = nx1; }
            }

            #pragma unroll
            for (int m = 0; m < 2; ++m) {
                int cA = (mtg + m) * 16 + gid;
                int cB = cA + 8;
                float bvA = bv[cA], bvB = bv[cB];
                #pragma unroll
                for (int nt = 0; nt < 8; ++nt) {
                    int gy = hi * Aa + nt;       // i = nt*8 + 2tg -> iy = nt
                    int gx = wi * Aa + 2 * tg;
                    if (gy < Hh && gx + 1 < Ww) {
                        size_t oA = ((size_t)cA * Hh + gy) * Ww + gx;
                        size_t oB = ((size_t)cB * Hh + gy) * Ww + gx;
                        float2 rA = *(const float2*)(xb + oA);
                        float2 rB = *(const float2*)(xb + oB);
                        float2 sA, sB;
                        sA.x = gma * (d[m][nt][0] + bvA) + rA.x;
                        sA.y = gma * (d[m][nt][1] + bvA) + rA.y;
                        sB.x = gma * (d[m][nt][2] + bvB) + rB.x;
                        sB.y = gma * (d[m][nt][3] + bvB) + rB.y;
                        *(float2*)(ob + oA) = sA;
                        *(float2*)(ob + oB) = sB;
                    }
                }
            }
        }
    }
}

extern "C" void kernel_launch(void* const* d_in, const int* in_sizes, int n_in,
                              void* d_out, int out_size) {
    (void)in_sizes; (void)n_in; (void)out_size;
    const float* x     = (const float*)d_in[0];
    const float* Wq    = (const float*)d_in[1];
    const float* bq    = (const float*)d_in[2];
    const float* Wk    = (const float*)d_in[3];
    const float* bk    = (const float*)d_in[4];
    const float* Wv    = (const float*)d_in[5];
    const float* bv    = (const float*)d_in[6];
    const float* gamma = (const float*)d_in[7];
    float* out = (float*)d_out;

    cudaFuncSetAttribute(area_attn_kernel,
                         cudaFuncAttributeMaxDynamicSharedMemorySize, SMEM_BYTES);

    prep_pack<<<160, 256>>>(Wq, Wk, Wv);
    area_attn_kernel<<<2048, 256, SMEM_BYTES>>>(x, bq, bk, bv, gamma, out);
}